// round 5
// baseline (speedup 1.0000x reference)
#include <cuda_runtime.h>
#include <cuda_bf16.h>
#include <cstdint>

#define BATCH    32768
#define IN_DIM   256
#define HID      512
#define OUT_DIM  128
#define NSTEPS   40
#define DT       0.025f
#define HDT      0.0125f
#define DT6      (0.025f / 6.0f)

// ---------------- static device scratch ----------------
__device__ __align__(128) __nv_bfloat16 g_S0h[(size_t)BATCH * HID];
__device__ __align__(128) __nv_bfloat16 g_S0l[(size_t)BATCH * HID];
__device__ __align__(128) __nv_bfloat16 g_S1h[(size_t)BATCH * HID];
__device__ __align__(128) __nv_bfloat16 g_S1l[(size_t)BATCH * HID];
__device__ __align__(128) __nv_bfloat16 g_S2h[(size_t)BATCH * HID];
__device__ __align__(128) __nv_bfloat16 g_S2l[(size_t)BATCH * HID];
__device__ __align__(128) __nv_bfloat16 g_S3h[(size_t)BATCH * HID];
__device__ __align__(128) __nv_bfloat16 g_S3l[(size_t)BATCH * HID];
__device__ __align__(128) __nv_bfloat16 g_Wbig[(size_t)HID * 1536];  // [n][k']: Whi|Whi|Wlo
__device__ __align__(128) __nv_bfloat16 g_Ubig[(size_t)HID * 1536];  // [n][k']: Uhi|Uhi|Ulo
__device__ __align__(128) float g_drive[(size_t)BATCH * HID];
__device__ __align__(128) float g_itau[HID];

__device__ __forceinline__ __nv_bfloat16* Sh_ptr(int i) {
  switch (i) { case 0: return g_S0h; case 1: return g_S1h; case 2: return g_S2h; default: return g_S3h; }
}
__device__ __forceinline__ __nv_bfloat16* Sl_ptr(int i) {
  switch (i) { case 0: return g_S0l; case 1: return g_S1l; case 2: return g_S2l; default: return g_S3l; }
}

// ---------------- helpers ----------------
__device__ __forceinline__ uint32_t smem_u32(const void* p) {
  uint32_t a;
  asm("{ .reg .u64 t; cvta.to.shared.u64 t, %1; cvt.u32.u64 %0, t; }" : "=r"(a) : "l"(p));
  return a;
}
__device__ __forceinline__ void cp16(uint32_t dst, const void* src) {
  asm volatile("cp.async.cg.shared.global [%0], [%1], 16;" :: "r"(dst), "l"(src) : "memory");
}
#define CP_COMMIT() asm volatile("cp.async.commit_group;" ::: "memory")
#define CP_WAIT1()  asm volatile("cp.async.wait_group 1;" ::: "memory")

#define LDSM4(r0, r1, r2, r3, a) \
  asm volatile("ldmatrix.sync.aligned.m8n8.x4.shared.b16 {%0,%1,%2,%3}, [%4];" \
               : "=r"(r0), "=r"(r1), "=r"(r2), "=r"(r3) : "r"(a))

#define MMA16816(d, a, b0, b1) \
  asm volatile("mma.sync.aligned.m16n8k16.row.col.f32.bf16.bf16.f32 " \
               "{%0,%1,%2,%3},{%4,%5,%6,%7},{%8,%9},{%0,%1,%2,%3};" \
               : "+f"((d)[0]), "+f"((d)[1]), "+f"((d)[2]), "+f"((d)[3]) \
               : "r"((a)[0]), "r"((a)[1]), "r"((a)[2]), "r"((a)[3]), "r"(b0), "r"(b1))

__device__ __forceinline__ float tanh_fast(float x) {
  float e = __expf(2.0f * x);
  return 1.0f - __fdividef(2.0f, e + 1.0f);
}

// ---------------- prep: W/U -> [hi | hi | lo] bf16, itau ----------------
__global__ void k_prep(const float* __restrict__ W, const float* __restrict__ U,
                       const float* __restrict__ tau) {
  int idx = blockIdx.x * 256 + threadIdx.x;           // 2*512*1536 total
  const int HALF = 512 * 1536;
  int h = (idx >= HALF) ? 1 : 0;
  int j = idx - h * HALF;
  int n = j / 1536, k = j % 1536;
  int kk = k & 511, region = k >> 9;
  const float* src = h ? U : W;
  __nv_bfloat16* dst = h ? g_Ubig : g_Wbig;
  float w = src[n * 512 + kk];
  __nv_bfloat16 hi = __float2bfloat16(w);
  dst[j] = (region < 2) ? hi : __float2bfloat16(w - __bfloat162float(hi));
  if (idx < HID) g_itau[idx] = 1.0f / tau[idx];
}

// ---------------- fp32 microtile GEMM (k_in / k_head) ----------------
template <int K>
__device__ __forceinline__ void gemm_tile(const float* __restrict__ As,
                                          const float* __restrict__ Bg,
                                          int row0, int col0, float acc[4][16]) {
#pragma unroll
  for (int i = 0; i < 4; i++)
#pragma unroll
    for (int j = 0; j < 16; j++) acc[i][j] = 0.f;
#pragma unroll 1
  for (int k = 0; k < K; k += 4) {
    float4 a[4];
#pragma unroll
    for (int kk = 0; kk < 4; kk++)
      a[kk] = *reinterpret_cast<const float4*>(As + (k + kk) * 32 + row0);
    float4 bb[16];
#pragma unroll
    for (int j = 0; j < 16; j++)
      bb[j] = *reinterpret_cast<const float4*>(Bg + (size_t)(col0 + j) * K + k);
#pragma unroll
    for (int j = 0; j < 16; j++) {
      float bv[4] = {bb[j].x, bb[j].y, bb[j].z, bb[j].w};
#pragma unroll
      for (int kk = 0; kk < 4; kk++) {
        acc[0][j] = fmaf(a[kk].x, bv[kk], acc[0][j]);
        acc[1][j] = fmaf(a[kk].y, bv[kk], acc[1][j]);
        acc[2][j] = fmaf(a[kk].z, bv[kk], acc[2][j]);
        acc[3][j] = fmaf(a[kk].w, bv[kk], acc[3][j]);
      }
    }
  }
}

// u = x @ Wx^T + bx ; writes S0 (h0 = u) as bf16 hi/lo
__global__ void __launch_bounds__(256, 1)
k_in(const float* __restrict__ x, const float* __restrict__ Wx,
     const float* __restrict__ bx) {
  extern __shared__ float sm[];
  const int tid = threadIdx.x, b0 = blockIdx.x * 32;
  for (int idx = tid; idx < 32 * IN_DIM; idx += 256) {
    int m = idx >> 8, k = idx & 255;
    sm[k * 32 + m] = x[(size_t)(b0 + m) * IN_DIM + k];
  }
  __syncthreads();
  const int row0 = (tid & 7) * 4, col0 = (tid >> 3) * 16;
  float acc[4][16];
  gemm_tile<IN_DIM>(sm, Wx, row0, col0, acc);
#pragma unroll
  for (int j = 0; j < 16; j++) {
    float bxi = bx[col0 + j];
#pragma unroll
    for (int i = 0; i < 4; i++) {
      float v = acc[i][j] + bxi;
      size_t ix = (size_t)(b0 + row0 + i) * HID + col0 + j;
      __nv_bfloat16 hi = __float2bfloat16(v);
      g_S0h[ix] = hi;
      g_S0l[ix] = __float2bfloat16(v - __bfloat162float(hi));
    }
  }
}

// out = h @ Wf^T + bf  (h = S0 hi+lo)
__global__ void __launch_bounds__(256, 1)
k_head(const float* __restrict__ Wf, const float* __restrict__ bf,
       float* __restrict__ out) {
  extern __shared__ float sm[];
  const int tid = threadIdx.x, b0 = blockIdx.x * 32;
  for (int idx = tid; idx < 32 * HID; idx += 256) {
    int m = idx >> 9, k = idx & 511;
    size_t ix = (size_t)(b0 + m) * HID + k;
    sm[k * 32 + m] = __bfloat162float(g_S0h[ix]) + __bfloat162float(g_S0l[ix]);
  }
  __syncthreads();
  const int row0 = (tid & 7) * 4, oc0 = (tid >> 3) * 4;
  float acc[4][4];
#pragma unroll
  for (int i = 0; i < 4; i++)
#pragma unroll
    for (int j = 0; j < 4; j++) acc[i][j] = 0.f;
#pragma unroll 1
  for (int k = 0; k < HID; k += 4) {
    float4 a[4];
#pragma unroll
    for (int kk = 0; kk < 4; kk++)
      a[kk] = *reinterpret_cast<const float4*>(sm + (k + kk) * 32 + row0);
#pragma unroll
    for (int j = 0; j < 4; j++) {
      float4 bb = *reinterpret_cast<const float4*>(Wf + (size_t)(oc0 + j) * HID + k);
      float bv[4] = {bb.x, bb.y, bb.z, bb.w};
#pragma unroll
      for (int kk = 0; kk < 4; kk++) {
        acc[0][j] = fmaf(a[kk].x, bv[kk], acc[0][j]);
        acc[1][j] = fmaf(a[kk].y, bv[kk], acc[1][j]);
        acc[2][j] = fmaf(a[kk].z, bv[kk], acc[2][j]);
        acc[3][j] = fmaf(a[kk].w, bv[kk], acc[3][j]);
      }
    }
  }
#pragma unroll
  for (int i = 0; i < 4; i++) {
    float4 o = make_float4(acc[i][0] + bf[oc0 + 0], acc[i][1] + bf[oc0 + 1],
                           acc[i][2] + bf[oc0 + 2], acc[i][3] + bf[oc0 + 3]);
    *reinterpret_cast<float4*>(out + (size_t)(b0 + row0 + i) * OUT_DIM + oc0) = o;
  }
}

// ---------------- HMMA GEMM kernel (stages + drive) ----------------
// MODE 0..3: RK4 stage. MODE 4: drive = u @ U^T + b.
// 512 threads, 16 warps (4M x 4N, 32x32 warp tiles), 128 rows/CTA,
// 4 n-chunks of 128, K chunk = 128 (12 chunks for K'=1536), 3-stage cp.async.
#define KCH      128
#define NCHUNK   12
#define APITCH   272             /* 256B row + 32B pad (bank shift 4) */
#define ASTG     34816           /* 128*272 */
#define SSTRIDE  69632           /* A + B per stage */
#define ST_SMEM  (3 * SSTRIDE)

template <int MODE>
__global__ void __launch_bounds__(512, 1) k_gemm(const float* __restrict__ bvec) {
  extern __shared__ __align__(128) char smem[];
  const uint32_t sb = smem_u32(smem);
  const int tid = threadIdx.x;
  const int lane = tid & 31, wid = tid >> 5;
  const int warp_m = wid & 3;            // 4 warps x 32 rows
  const int warp_n = wid >> 2;           // 4 warps x 32 cols
  const int b0 = blockIdx.x * 128;
  const int lr = lane & 15, lc = lane >> 4;

  const __nv_bfloat16* shi = (MODE == 4) ? g_S0h : Sh_ptr(MODE);
  const __nv_bfloat16* slo = (MODE == 4) ? g_S0l : Sl_ptr(MODE);
  const __nv_bfloat16* Bmat = (MODE == 4) ? g_Ubig : g_Wbig;
  __nv_bfloat16* dsth = (MODE == 4) ? g_S0h : Sh_ptr((MODE + 1) & 3);
  __nv_bfloat16* dstl = (MODE == 4) ? g_S0l : Sl_ptr((MODE + 1) & 3);

  // feeder decomposition: each thread owns rows tr+32j, 16B segment tc
  const int tr = tid >> 4;               // 0..31
  const int tc = tid & 15;               // 0..15
  const uint32_t a_dst0 = tr * APITCH + tc * 16;
  const uint32_t b_dst0 = ASTG + a_dst0;
  // LDSM / MMA addressing
  const uint32_t a_off = (warp_m * 32 + lr) * APITCH + lc * 16;
  const uint32_t b_off = ASTG + (warp_n * 32 + lr) * APITCH + lc * 16;
  const uint32_t s_last = sb + 2 * SSTRIDE;

#pragma unroll 1
  for (int nc = 0; nc < 4; ++nc) {
    const int n0 = nc * 128;
    const __nv_bfloat16* brow_base = Bmat + (size_t)(n0 + tr) * 1536 + tc * 8;
    float acc[2][4][4];
#pragma unroll
    for (int i = 0; i < 2; i++)
#pragma unroll
      for (int j = 0; j < 4; j++)
#pragma unroll
        for (int q = 0; q < 4; q++) acc[i][j][q] = 0.f;

    // ---- feeder lambda (manual): load chunk kc into stage base ----
#define LD_CHUNK(stg, kc_) do {                                               \
    const int _kc = (kc_);                                                    \
    const int _region = _kc >> 2;                                             \
    const __nv_bfloat16* _as = (_region == 1) ? slo : shi;                    \
    const int _k0 = (_kc & 3) << 7;                                           \
    const __nv_bfloat16* _arow = _as + (((uint32_t)(b0 + tr)) << 9) + _k0 + tc * 8; \
    const __nv_bfloat16* _brow = brow_base + (_kc << 7);                      \
    uint32_t _ad = (stg) + a_dst0, _bd = (stg) + b_dst0;                      \
    _Pragma("unroll")                                                         \
    for (int _j = 0; _j < 4; _j++) {                                          \
      cp16(_ad, _arow); cp16(_bd, _brow);                                     \
      _ad += 32 * APITCH; _bd += 32 * APITCH;                                 \
      _arow += 32 * 512;  _brow += 32 * 1536;                                 \
    }                                                                         \
  } while (0)

    LD_CHUNK(sb, 0); CP_COMMIT();
    LD_CHUNK(sb + SSTRIDE, 1); CP_COMMIT();

    uint32_t rd = sb, wr = sb + 2 * SSTRIDE;
#pragma unroll 1
    for (int kc = 0; kc < NCHUNK; ++kc) {
      CP_WAIT1();
      __syncthreads();
      const uint32_t ab = rd + a_off;
      const uint32_t bb = rd + b_off;
      // software-pipelined fragment loads over 8 k16 groups
      uint32_t af[2][2][4], bfm[2][2][4];
      LDSM4(af[0][0][0], af[0][0][1], af[0][0][2], af[0][0][3], ab);
      LDSM4(af[0][1][0], af[0][1][1], af[0][1][2], af[0][1][3], ab + 16 * APITCH);
      LDSM4(bfm[0][0][0], bfm[0][0][1], bfm[0][0][2], bfm[0][0][3], bb);
      LDSM4(bfm[0][1][0], bfm[0][1][1], bfm[0][1][2], bfm[0][1][3], bb + 16 * APITCH);
#pragma unroll
      for (int kk = 0; kk < 8; kk++) {
        const int cur = kk & 1, nxt = cur ^ 1;
        if (kk < 7) {
          const uint32_t ko = (kk + 1) * 32;
          LDSM4(af[nxt][0][0], af[nxt][0][1], af[nxt][0][2], af[nxt][0][3], ab + ko);
          LDSM4(af[nxt][1][0], af[nxt][1][1], af[nxt][1][2], af[nxt][1][3], ab + 16 * APITCH + ko);
          LDSM4(bfm[nxt][0][0], bfm[nxt][0][1], bfm[nxt][0][2], bfm[nxt][0][3], bb + ko);
          LDSM4(bfm[nxt][1][0], bfm[nxt][1][1], bfm[nxt][1][2], bfm[nxt][1][3], bb + 16 * APITCH + ko);
        }
#pragma unroll
        for (int fm = 0; fm < 2; fm++)
#pragma unroll
          for (int fn = 0; fn < 2; fn++) {
            MMA16816(acc[fm][2 * fn],     af[cur][fm], bfm[cur][fn][0], bfm[cur][fn][2]);
            MMA16816(acc[fm][2 * fn + 1], af[cur][fm], bfm[cur][fn][1], bfm[cur][fn][3]);
          }
      }
      if (kc < NCHUNK - 2) LD_CHUNK(wr, kc + 2);
      CP_COMMIT();
      rd = (rd == s_last) ? sb : rd + SSTRIDE;
      wr = (wr == s_last) ? sb : wr + SSTRIDE;
    }
#undef LD_CHUNK

    // ---- fused epilogue on register fragments ----
    const int rq = lane >> 2, cq = (lane & 3) * 2;
#pragma unroll
    for (int fn = 0; fn < 4; fn++) {
      const int nn = n0 + warp_n * 32 + fn * 8 + cq;
#pragma unroll
      for (int fm = 0; fm < 2; fm++) {
#pragma unroll
        for (int half = 0; half < 2; half++) {
          const int r = b0 + warp_m * 32 + fm * 16 + rq + half * 8;
          const uint32_t ix = ((uint32_t)r << 9) + nn;
          const float c0 = acc[fm][fn][half * 2];
          const float c1 = acc[fm][fn][half * 2 + 1];
          if (MODE == 4) {
            float2 bv = *reinterpret_cast<const float2*>(bvec + nn);
            float2 o = make_float2(c0 + bv.x, c1 + bv.y);
            *reinterpret_cast<float2*>(g_drive + ix) = o;
          } else {
            const float2 it2 = *reinterpret_cast<const float2*>(g_itau + nn);
            float2 dr = *reinterpret_cast<const float2*>(g_drive + ix);
            __nv_bfloat162 sh2 = *reinterpret_cast<const __nv_bfloat162*>(shi + ix);
            __nv_bfloat162 sl2 = *reinterpret_cast<const __nv_bfloat162*>(slo + ix);
            float s0 = __bfloat162float(sh2.x) + __bfloat162float(sl2.x);
            float s1 = __bfloat162float(sh2.y) + __bfloat162float(sl2.y);
            float t0 = tanh_fast(c0 + dr.x);
            float t1 = tanh_fast(c1 + dr.y);
            float k0 = (t0 - s0) * it2.x;
            float k1 = (t1 - s1) * it2.y;
            float v0, v1;
            if (MODE == 0) {
              v0 = s0 + HDT * k0; v1 = s1 + HDT * k1;     // s2 = h + dt/2 k1
            } else {
              __nv_bfloat162 hh2 = *reinterpret_cast<const __nv_bfloat162*>(g_S0h + ix);
              __nv_bfloat162 hl2 = *reinterpret_cast<const __nv_bfloat162*>(g_S0l + ix);
              float h0 = __bfloat162float(hh2.x) + __bfloat162float(hl2.x);
              float h1 = __bfloat162float(hh2.y) + __bfloat162float(hl2.y);
              if (MODE == 1)      { v0 = h0 + HDT * k0; v1 = h1 + HDT * k1; }  // s3
              else if (MODE == 2) { v0 = h0 + DT * k0;  v1 = h1 + DT * k1;  }  // s4
              else {
                __nv_bfloat162 ah2 = *reinterpret_cast<const __nv_bfloat162*>(g_S1h + ix);
                __nv_bfloat162 al2 = *reinterpret_cast<const __nv_bfloat162*>(g_S1l + ix);
                __nv_bfloat162 bh2 = *reinterpret_cast<const __nv_bfloat162*>(g_S2h + ix);
                __nv_bfloat162 bl2 = *reinterpret_cast<const __nv_bfloat162*>(g_S2l + ix);
                float s20 = __bfloat162float(ah2.x) + __bfloat162float(al2.x);
                float s21 = __bfloat162float(ah2.y) + __bfloat162float(al2.y);
                float s30 = __bfloat162float(bh2.x) + __bfloat162float(bl2.x);
                float s31 = __bfloat162float(bh2.y) + __bfloat162float(bl2.y);
                v0 = h0 + (1.0f / 3.0f) * (s20 - h0) + (2.0f / 3.0f) * (s30 - h0)
                        + (1.0f / 3.0f) * (s0 - h0) + DT6 * k0;  // h_{n+1}
                v1 = h1 + (1.0f / 3.0f) * (s21 - h1) + (2.0f / 3.0f) * (s31 - h1)
                        + (1.0f / 3.0f) * (s1 - h1) + DT6 * k1;
              }
            }
            __nv_bfloat16 hi0 = __float2bfloat16(v0);
            __nv_bfloat16 hi1 = __float2bfloat16(v1);
            __nv_bfloat162 oh; oh.x = hi0; oh.y = hi1;
            __nv_bfloat162 ol;
            ol.x = __float2bfloat16(v0 - __bfloat162float(hi0));
            ol.y = __float2bfloat16(v1 - __bfloat162float(hi1));
            *reinterpret_cast<__nv_bfloat162*>(dsth + ix) = oh;
            *reinterpret_cast<__nv_bfloat162*>(dstl + ix) = ol;
          }
        }
      }
    }
    __syncthreads();   // stage buffers reused next nc
  }
}

// ---------------- launcher ----------------
extern "C" void kernel_launch(void* const* d_in, const int* in_sizes, int n_in,
                              void* d_out, int out_size) {
  (void)in_sizes; (void)n_in; (void)out_size;
  const float* x    = (const float*)d_in[0];
  const float* Wx   = (const float*)d_in[1];
  const float* bx   = (const float*)d_in[2];
  const float* W    = (const float*)d_in[3];
  const float* U    = (const float*)d_in[4];
  const float* bvec = (const float*)d_in[5];
  const float* tau  = (const float*)d_in[6];
  const float* Wf   = (const float*)d_in[7];
  const float* bf   = (const float*)d_in[8];
  float* out = (float*)d_out;

  cudaFuncSetAttribute(k_gemm<0>, cudaFuncAttributeMaxDynamicSharedMemorySize, ST_SMEM);
  cudaFuncSetAttribute(k_gemm<1>, cudaFuncAttributeMaxDynamicSharedMemorySize, ST_SMEM);
  cudaFuncSetAttribute(k_gemm<2>, cudaFuncAttributeMaxDynamicSharedMemorySize, ST_SMEM);
  cudaFuncSetAttribute(k_gemm<3>, cudaFuncAttributeMaxDynamicSharedMemorySize, ST_SMEM);
  cudaFuncSetAttribute(k_gemm<4>, cudaFuncAttributeMaxDynamicSharedMemorySize, ST_SMEM);
  cudaFuncSetAttribute(k_head,  cudaFuncAttributeMaxDynamicSharedMemorySize, 65536);
  cudaFuncSetAttribute(k_in,    cudaFuncAttributeMaxDynamicSharedMemorySize, 32768);

  k_prep<<<(2 * 512 * 1536) / 256, 256>>>(W, U, tau);
  k_in<<<BATCH / 32, 256, 32768>>>(x, Wx, bx);
  k_gemm<4><<<BATCH / 128, 512, ST_SMEM>>>(bvec);        // drive
  for (int step = 0; step < NSTEPS; ++step) {
    k_gemm<0><<<BATCH / 128, 512, ST_SMEM>>>(nullptr);
    k_gemm<1><<<BATCH / 128, 512, ST_SMEM>>>(nullptr);
    k_gemm<2><<<BATCH / 128, 512, ST_SMEM>>>(nullptr);
    k_gemm<3><<<BATCH / 128, 512, ST_SMEM>>>(nullptr);
  }
  k_head<<<BATCH / 32, 256, 65536>>>(Wf, bf, out);
}

// round 6
// speedup vs baseline: 1.0869x; 1.0869x over previous
#include <cuda_runtime.h>
#include <cuda_bf16.h>
#include <cstdint>

#define BATCH    32768
#define IN_DIM   256
#define HID      512
#define OUT_DIM  128
#define NSTEPS   40
#define DT       0.025f
#define HDT      0.0125f
#define DT6      (0.025f / 6.0f)

// ---------------- static device scratch ----------------
__device__ __align__(128) __nv_bfloat16 g_S0h[(size_t)BATCH * HID];
__device__ __align__(128) __nv_bfloat16 g_S0l[(size_t)BATCH * HID];
__device__ __align__(128) __nv_bfloat16 g_S1h[(size_t)BATCH * HID];
__device__ __align__(128) __nv_bfloat16 g_S1l[(size_t)BATCH * HID];
__device__ __align__(128) __nv_bfloat16 g_S2h[(size_t)BATCH * HID];
__device__ __align__(128) __nv_bfloat16 g_S2l[(size_t)BATCH * HID];
__device__ __align__(128) __nv_bfloat16 g_S3h[(size_t)BATCH * HID];
__device__ __align__(128) __nv_bfloat16 g_S3l[(size_t)BATCH * HID];
__device__ __align__(128) __nv_bfloat16 g_Wbig[(size_t)HID * 1536];  // [n][k']: Whi|Whi|Wlo
__device__ __align__(128) __nv_bfloat16 g_Ubig[(size_t)HID * 1536];  // [n][k']: Uhi|Uhi|Ulo
__device__ __align__(128) float g_drive[(size_t)BATCH * HID];
__device__ __align__(128) float g_itau[HID];

__device__ __forceinline__ __nv_bfloat16* Sh_ptr(int i) {
  switch (i) { case 0: return g_S0h; case 1: return g_S1h; case 2: return g_S2h; default: return g_S3h; }
}
__device__ __forceinline__ __nv_bfloat16* Sl_ptr(int i) {
  switch (i) { case 0: return g_S0l; case 1: return g_S1l; case 2: return g_S2l; default: return g_S3l; }
}

// ---------------- helpers ----------------
__device__ __forceinline__ uint32_t smem_u32(const void* p) {
  uint32_t a;
  asm("{ .reg .u64 t; cvta.to.shared.u64 t, %1; cvt.u32.u64 %0, t; }" : "=r"(a) : "l"(p));
  return a;
}
__device__ __forceinline__ void cp16(uint32_t dst, const void* src) {
  asm volatile("cp.async.cg.shared.global [%0], [%1], 16;" :: "r"(dst), "l"(src) : "memory");
}
#define CP_COMMIT() asm volatile("cp.async.commit_group;" ::: "memory")
#define CP_WAIT1()  asm volatile("cp.async.wait_group 1;" ::: "memory")

#define LDSM4(r0, r1, r2, r3, a) \
  asm volatile("ldmatrix.sync.aligned.m8n8.x4.shared.b16 {%0,%1,%2,%3}, [%4];" \
               : "=r"(r0), "=r"(r1), "=r"(r2), "=r"(r3) : "r"(a))

#define MMA16816(d, a, b0, b1) \
  asm volatile("mma.sync.aligned.m16n8k16.row.col.f32.bf16.bf16.f32 " \
               "{%0,%1,%2,%3},{%4,%5,%6,%7},{%8,%9},{%0,%1,%2,%3};" \
               : "+f"((d)[0]), "+f"((d)[1]), "+f"((d)[2]), "+f"((d)[3]) \
               : "r"((a)[0]), "r"((a)[1]), "r"((a)[2]), "r"((a)[3]), "r"(b0), "r"(b1))

__device__ __forceinline__ float tanh_fast(float x) {
  float e = __expf(2.0f * x);
  return 1.0f - __fdividef(2.0f, e + 1.0f);
}

// ---------------- prep: W/U -> [hi | hi | lo] bf16, itau ----------------
__global__ void k_prep(const float* __restrict__ W, const float* __restrict__ U,
                       const float* __restrict__ tau) {
  int idx = blockIdx.x * 256 + threadIdx.x;           // 2*512*1536 total
  const int HALF = 512 * 1536;
  int h = (idx >= HALF) ? 1 : 0;
  int j = idx - h * HALF;
  int n = j / 1536, k = j % 1536;
  int kk = k & 511, region = k >> 9;
  const float* src = h ? U : W;
  __nv_bfloat16* dst = h ? g_Ubig : g_Wbig;
  float w = src[n * 512 + kk];
  __nv_bfloat16 hi = __float2bfloat16(w);
  dst[j] = (region < 2) ? hi : __float2bfloat16(w - __bfloat162float(hi));
  if (idx < HID) g_itau[idx] = 1.0f / tau[idx];
}

// ---------------- fp32 microtile GEMM (k_in / k_head) ----------------
template <int K>
__device__ __forceinline__ void gemm_tile(const float* __restrict__ As,
                                          const float* __restrict__ Bg,
                                          int row0, int col0, float acc[4][16]) {
#pragma unroll
  for (int i = 0; i < 4; i++)
#pragma unroll
    for (int j = 0; j < 16; j++) acc[i][j] = 0.f;
#pragma unroll 1
  for (int k = 0; k < K; k += 4) {
    float4 a[4];
#pragma unroll
    for (int kk = 0; kk < 4; kk++)
      a[kk] = *reinterpret_cast<const float4*>(As + (k + kk) * 32 + row0);
    float4 bb[16];
#pragma unroll
    for (int j = 0; j < 16; j++)
      bb[j] = *reinterpret_cast<const float4*>(Bg + (size_t)(col0 + j) * K + k);
#pragma unroll
    for (int j = 0; j < 16; j++) {
      float bv[4] = {bb[j].x, bb[j].y, bb[j].z, bb[j].w};
#pragma unroll
      for (int kk = 0; kk < 4; kk++) {
        acc[0][j] = fmaf(a[kk].x, bv[kk], acc[0][j]);
        acc[1][j] = fmaf(a[kk].y, bv[kk], acc[1][j]);
        acc[2][j] = fmaf(a[kk].z, bv[kk], acc[2][j]);
        acc[3][j] = fmaf(a[kk].w, bv[kk], acc[3][j]);
      }
    }
  }
}

// u = x @ Wx^T + bx ; writes S0 (h0 = u) as bf16 hi/lo
__global__ void __launch_bounds__(256, 1)
k_in(const float* __restrict__ x, const float* __restrict__ Wx,
     const float* __restrict__ bx) {
  extern __shared__ float sm[];
  const int tid = threadIdx.x, b0 = blockIdx.x * 32;
  for (int idx = tid; idx < 32 * IN_DIM; idx += 256) {
    int m = idx >> 8, k = idx & 255;
    sm[k * 32 + m] = x[(size_t)(b0 + m) * IN_DIM + k];
  }
  __syncthreads();
  const int row0 = (tid & 7) * 4, col0 = (tid >> 3) * 16;
  float acc[4][16];
  gemm_tile<IN_DIM>(sm, Wx, row0, col0, acc);
#pragma unroll
  for (int j = 0; j < 16; j++) {
    float bxi = bx[col0 + j];
#pragma unroll
    for (int i = 0; i < 4; i++) {
      float v = acc[i][j] + bxi;
      size_t ix = (size_t)(b0 + row0 + i) * HID + col0 + j;
      __nv_bfloat16 hi = __float2bfloat16(v);
      g_S0h[ix] = hi;
      g_S0l[ix] = __float2bfloat16(v - __bfloat162float(hi));
    }
  }
}

// out = h @ Wf^T + bf  (h = S0 hi+lo)
__global__ void __launch_bounds__(256, 1)
k_head(const float* __restrict__ Wf, const float* __restrict__ bf,
       float* __restrict__ out) {
  extern __shared__ float sm[];
  const int tid = threadIdx.x, b0 = blockIdx.x * 32;
  for (int idx = tid; idx < 32 * HID; idx += 256) {
    int m = idx >> 9, k = idx & 511;
    size_t ix = (size_t)(b0 + m) * HID + k;
    sm[k * 32 + m] = __bfloat162float(g_S0h[ix]) + __bfloat162float(g_S0l[ix]);
  }
  __syncthreads();
  const int row0 = (tid & 7) * 4, oc0 = (tid >> 3) * 4;
  float acc[4][4];
#pragma unroll
  for (int i = 0; i < 4; i++)
#pragma unroll
    for (int j = 0; j < 4; j++) acc[i][j] = 0.f;
#pragma unroll 1
  for (int k = 0; k < HID; k += 4) {
    float4 a[4];
#pragma unroll
    for (int kk = 0; kk < 4; kk++)
      a[kk] = *reinterpret_cast<const float4*>(sm + (k + kk) * 32 + row0);
#pragma unroll
    for (int j = 0; j < 4; j++) {
      float4 bb = *reinterpret_cast<const float4*>(Wf + (size_t)(oc0 + j) * HID + k);
      float bv[4] = {bb.x, bb.y, bb.z, bb.w};
#pragma unroll
      for (int kk = 0; kk < 4; kk++) {
        acc[0][j] = fmaf(a[kk].x, bv[kk], acc[0][j]);
        acc[1][j] = fmaf(a[kk].y, bv[kk], acc[1][j]);
        acc[2][j] = fmaf(a[kk].z, bv[kk], acc[2][j]);
        acc[3][j] = fmaf(a[kk].w, bv[kk], acc[3][j]);
      }
    }
  }
#pragma unroll
  for (int i = 0; i < 4; i++) {
    float4 o = make_float4(acc[i][0] + bf[oc0 + 0], acc[i][1] + bf[oc0 + 1],
                           acc[i][2] + bf[oc0 + 2], acc[i][3] + bf[oc0 + 3]);
    *reinterpret_cast<float4*>(out + (size_t)(b0 + row0 + i) * OUT_DIM + oc0) = o;
  }
}

// ---------------- HMMA GEMM kernel (stages + drive) ----------------
// MODE 0..3: RK4 stage. MODE 4: drive = u @ U^T + b.
// 512 threads, 16 warps (4M x 4N), 128 rows/CTA, 4 n-chunks of 128.
// 3-stage cp.async pipeline, K chunk = 64 (24 chunks for K'=1536).
// __launch_bounds__(512, 2): cap regs at 64 so 2 CTAs co-reside per SM.
#define APITCH   144
#define ASTG     18432           /* 128*144 */
#define SSTRIDE  36864           /* A + B per stage */
#define NSTG     3
#define ST_SMEM  (NSTG * SSTRIDE)

__device__ __forceinline__ void ld_chunk(uint32_t stg_base, int b0, int n0, int kc,
                                         int tid, const __nv_bfloat16* shi,
                                         const __nv_bfloat16* slo,
                                         const __nv_bfloat16* Bmat) {
  const __nv_bfloat16* asrc = ((kc >> 3) == 1) ? slo : shi;
  const int k0 = (kc & 7) << 6;
  const int kg = kc << 6;
#pragma unroll
  for (int j = 0; j < 2; j++) {
    int i = tid + j * 512;
    int r = i >> 3, c = i & 7;
    cp16(stg_base + r * APITCH + c * 16,
         asrc + (((size_t)(b0 + r)) << 9) + k0 + c * 8);
    cp16(stg_base + ASTG + r * APITCH + c * 16,
         Bmat + (size_t)(n0 + r) * 1536 + kg + c * 8);
  }
}

template <int MODE>
__global__ void __launch_bounds__(512, 2) k_gemm(const float* __restrict__ bvec) {
  extern __shared__ __align__(128) char smem[];
  const uint32_t sb = smem_u32(smem);
  const int tid = threadIdx.x;
  const int lane = tid & 31, wid = tid >> 5;
  const int warp_m = wid & 3;            // 4 warps x 32 rows
  const int warp_n = wid >> 2;           // 4 warps x 32 cols
  const int b0 = blockIdx.x * 128;
  const int lr = lane & 15, lc = lane >> 4;

  const __nv_bfloat16* shi = (MODE == 4) ? g_S0h : Sh_ptr(MODE);
  const __nv_bfloat16* slo = (MODE == 4) ? g_S0l : Sl_ptr(MODE);
  const __nv_bfloat16* Bmat = (MODE == 4) ? g_Ubig : g_Wbig;
  __nv_bfloat16* dsth = (MODE == 4) ? g_S0h : Sh_ptr((MODE + 1) & 3);
  __nv_bfloat16* dstl = (MODE == 4) ? g_S0l : Sl_ptr((MODE + 1) & 3);

  const uint32_t a_off = (warp_m * 32 + lr) * APITCH + lc * 16;
  const uint32_t b_off = ASTG + (warp_n * 32 + lr) * APITCH + lc * 16;
  const uint32_t s_last = sb + 2 * SSTRIDE;

#pragma unroll 1
  for (int nc = 0; nc < 4; ++nc) {
    const int n0 = nc * 128;
    float acc[2][4][4];
#pragma unroll
    for (int i = 0; i < 2; i++)
#pragma unroll
      for (int j = 0; j < 4; j++)
#pragma unroll
        for (int q = 0; q < 4; q++) acc[i][j][q] = 0.f;

    ld_chunk(sb, b0, n0, 0, tid, shi, slo, Bmat); CP_COMMIT();
    ld_chunk(sb + SSTRIDE, b0, n0, 1, tid, shi, slo, Bmat); CP_COMMIT();

    uint32_t rd = sb, wr = sb + 2 * SSTRIDE;
#pragma unroll 1
    for (int kc = 0; kc < 24; ++kc) {
      CP_WAIT1();
      __syncthreads();
      const uint32_t ab = rd + a_off;
      const uint32_t bb = rd + b_off;
#pragma unroll
      for (int kk = 0; kk < 4; kk++) {
        uint32_t a[2][4], bfr[2][4];
        LDSM4(a[0][0], a[0][1], a[0][2], a[0][3], ab + kk * 32);
        LDSM4(a[1][0], a[1][1], a[1][2], a[1][3], ab + 16 * APITCH + kk * 32);
        LDSM4(bfr[0][0], bfr[0][1], bfr[0][2], bfr[0][3], bb + kk * 32);
        LDSM4(bfr[1][0], bfr[1][1], bfr[1][2], bfr[1][3], bb + 16 * APITCH + kk * 32);
#pragma unroll
        for (int fm = 0; fm < 2; fm++)
#pragma unroll
          for (int fn = 0; fn < 2; fn++) {
            MMA16816(acc[fm][2 * fn],     a[fm], bfr[fn][0], bfr[fn][2]);
            MMA16816(acc[fm][2 * fn + 1], a[fm], bfr[fn][1], bfr[fn][3]);
          }
      }
      if (kc < 22) ld_chunk(wr, b0, n0, kc + 2, tid, shi, slo, Bmat);
      CP_COMMIT();
      rd = (rd == s_last) ? sb : rd + SSTRIDE;
      wr = (wr == s_last) ? sb : wr + SSTRIDE;
    }

    // ---- fused epilogue on register fragments ----
    const int rq = lane >> 2, cq = (lane & 3) * 2;
#pragma unroll
    for (int fn = 0; fn < 4; fn++) {
      const int nn = n0 + warp_n * 32 + fn * 8 + cq;
#pragma unroll
      for (int fm = 0; fm < 2; fm++) {
#pragma unroll
        for (int half = 0; half < 2; half++) {
          const int r = b0 + warp_m * 32 + fm * 16 + rq + half * 8;
          const size_t ix = ((size_t)r << 9) + nn;
          const float c0 = acc[fm][fn][half * 2];
          const float c1 = acc[fm][fn][half * 2 + 1];
          if (MODE == 4) {
            float2 bv = *reinterpret_cast<const float2*>(bvec + nn);
            float2 o = make_float2(c0 + bv.x, c1 + bv.y);
            *reinterpret_cast<float2*>(g_drive + ix) = o;
          } else {
            const float2 it2 = *reinterpret_cast<const float2*>(g_itau + nn);
            float2 dr = *reinterpret_cast<const float2*>(g_drive + ix);
            __nv_bfloat162 sh2 = *reinterpret_cast<const __nv_bfloat162*>(shi + ix);
            __nv_bfloat162 sl2 = *reinterpret_cast<const __nv_bfloat162*>(slo + ix);
            float s0 = __bfloat162float(sh2.x) + __bfloat162float(sl2.x);
            float s1 = __bfloat162float(sh2.y) + __bfloat162float(sl2.y);
            float t0 = tanh_fast(c0 + dr.x);
            float t1 = tanh_fast(c1 + dr.y);
            float k0 = (t0 - s0) * it2.x;
            float k1 = (t1 - s1) * it2.y;
            float v0, v1;
            if (MODE == 0) {
              v0 = s0 + HDT * k0; v1 = s1 + HDT * k1;     // s2 = h + dt/2 k1
            } else {
              __nv_bfloat162 hh2 = *reinterpret_cast<const __nv_bfloat162*>(g_S0h + ix);
              __nv_bfloat162 hl2 = *reinterpret_cast<const __nv_bfloat162*>(g_S0l + ix);
              float h0 = __bfloat162float(hh2.x) + __bfloat162float(hl2.x);
              float h1 = __bfloat162float(hh2.y) + __bfloat162float(hl2.y);
              if (MODE == 1)      { v0 = h0 + HDT * k0; v1 = h1 + HDT * k1; }  // s3
              else if (MODE == 2) { v0 = h0 + DT * k0;  v1 = h1 + DT * k1;  }  // s4
              else {
                __nv_bfloat162 ah2 = *reinterpret_cast<const __nv_bfloat162*>(g_S1h + ix);
                __nv_bfloat162 al2 = *reinterpret_cast<const __nv_bfloat162*>(g_S1l + ix);
                __nv_bfloat162 bh2 = *reinterpret_cast<const __nv_bfloat162*>(g_S2h + ix);
                __nv_bfloat162 bl2 = *reinterpret_cast<const __nv_bfloat162*>(g_S2l + ix);
                float s20 = __bfloat162float(ah2.x) + __bfloat162float(al2.x);
                float s21 = __bfloat162float(ah2.y) + __bfloat162float(al2.y);
                float s30 = __bfloat162float(bh2.x) + __bfloat162float(bl2.x);
                float s31 = __bfloat162float(bh2.y) + __bfloat162float(bl2.y);
                v0 = h0 + (1.0f / 3.0f) * (s20 - h0) + (2.0f / 3.0f) * (s30 - h0)
                        + (1.0f / 3.0f) * (s0 - h0) + DT6 * k0;  // h_{n+1}
                v1 = h1 + (1.0f / 3.0f) * (s21 - h1) + (2.0f / 3.0f) * (s31 - h1)
                        + (1.0f / 3.0f) * (s1 - h1) + DT6 * k1;
              }
            }
            __nv_bfloat16 hi0 = __float2bfloat16(v0);
            __nv_bfloat16 hi1 = __float2bfloat16(v1);
            __nv_bfloat162 oh; oh.x = hi0; oh.y = hi1;
            __nv_bfloat162 ol;
            ol.x = __float2bfloat16(v0 - __bfloat162float(hi0));
            ol.y = __float2bfloat16(v1 - __bfloat162float(hi1));
            *reinterpret_cast<__nv_bfloat162*>(dsth + ix) = oh;
            *reinterpret_cast<__nv_bfloat162*>(dstl + ix) = ol;
          }
        }
      }
    }
    __syncthreads();   // stage buffers reused next nc
  }
}

// ---------------- launcher ----------------
extern "C" void kernel_launch(void* const* d_in, const int* in_sizes, int n_in,
                              void* d_out, int out_size) {
  (void)in_sizes; (void)n_in; (void)out_size;
  const float* x    = (const float*)d_in[0];
  const float* Wx   = (const float*)d_in[1];
  const float* bx   = (const float*)d_in[2];
  const float* W    = (const float*)d_in[3];
  const float* U    = (const float*)d_in[4];
  const float* bvec = (const float*)d_in[5];
  const float* tau  = (const float*)d_in[6];
  const float* Wf   = (const float*)d_in[7];
  const float* bf   = (const float*)d_in[8];
  float* out = (float*)d_out;

  cudaFuncSetAttribute(k_gemm<0>, cudaFuncAttributeMaxDynamicSharedMemorySize, ST_SMEM);
  cudaFuncSetAttribute(k_gemm<1>, cudaFuncAttributeMaxDynamicSharedMemorySize, ST_SMEM);
  cudaFuncSetAttribute(k_gemm<2>, cudaFuncAttributeMaxDynamicSharedMemorySize, ST_SMEM);
  cudaFuncSetAttribute(k_gemm<3>, cudaFuncAttributeMaxDynamicSharedMemorySize, ST_SMEM);
  cudaFuncSetAttribute(k_gemm<4>, cudaFuncAttributeMaxDynamicSharedMemorySize, ST_SMEM);
  cudaFuncSetAttribute(k_head,  cudaFuncAttributeMaxDynamicSharedMemorySize, 65536);
  cudaFuncSetAttribute(k_in,    cudaFuncAttributeMaxDynamicSharedMemorySize, 32768);

  k_prep<<<(2 * 512 * 1536) / 256, 256>>>(W, U, tau);
  k_in<<<BATCH / 32, 256, 32768>>>(x, Wx, bx);
  k_gemm<4><<<BATCH / 128, 512, ST_SMEM>>>(bvec);        // drive
  for (int step = 0; step < NSTEPS; ++step) {
    k_gemm<0><<<BATCH / 128, 512, ST_SMEM>>>(nullptr);
    k_gemm<1><<<BATCH / 128, 512, ST_SMEM>>>(nullptr);
    k_gemm<2><<<BATCH / 128, 512, ST_SMEM>>>(nullptr);
    k_gemm<3><<<BATCH / 128, 512, ST_SMEM>>>(nullptr);
  }
  k_head<<<BATCH / 32, 256, 65536>>>(Wf, bf, out);
}